// round 7
// baseline (speedup 1.0000x reference)
#include <cuda_runtime.h>
#include <cuda_bf16.h>
#include <cstdint>

#define NN 8192
#define FF 256

// ---- device scratch ----
__device__ __align__(16) float g_E[NN * FF];             // emb after iter0 (fp32)
__device__ __align__(16) __nv_bfloat16 g_Yt[FF * NN];    // Y^T bf16 [feature][row]
__device__ __align__(16) float g_Gp[32 * FF * FF];       // SYRK split-K partials
__device__ __align__(16) __nv_bfloat16 g_Gh[FF * FF];    // Gram bf16 (symmetric)
__device__ __align__(16) float g_s[2 * FF];              // colsum(Y) per iter
__device__ __align__(16) float g_m[FF];                  // m = Y^T d (iter1)
__device__ float g_r[NN];                                // per-row sumsq (iter0)
__device__ float g_rp[2 * NN];                           // per-row sumsq partials (iter1)
__device__ float g_alpha[NN];                            // per-row scale
__device__ float g_d[NN];                                // d_j = alpha_j*(src_j.s)
__device__ float g_Tp1[1024];                            // T partials iter0
__device__ float g_Tp2[128];                             // T partials iter1
__device__ float g_ab[4];                                // a0,b0,a1,b1

// ---- mma / ldmatrix helpers ----
__device__ __forceinline__ uint32_t smem_u32(const void* p) {
    return (uint32_t)__cvta_generic_to_shared(p);
}
__device__ __forceinline__ void ldsm4(uint32_t (&r)[4], uint32_t addr) {
    asm volatile("ldmatrix.sync.aligned.m8n8.x4.shared.b16 {%0,%1,%2,%3}, [%4];"
                 : "=r"(r[0]), "=r"(r[1]), "=r"(r[2]), "=r"(r[3]) : "r"(addr));
}
__device__ __forceinline__ void ldsm4t(uint32_t (&r)[4], uint32_t addr) {
    asm volatile("ldmatrix.sync.aligned.m8n8.x4.trans.shared.b16 {%0,%1,%2,%3}, [%4];"
                 : "=r"(r[0]), "=r"(r[1]), "=r"(r[2]), "=r"(r[3]) : "r"(addr));
}
__device__ __forceinline__ void mma16816(float* c, const uint32_t* a, uint32_t b0, uint32_t b1) {
    asm volatile("mma.sync.aligned.m16n8k16.row.col.f32.bf16.bf16.f32 "
                 "{%0,%1,%2,%3}, {%4,%5,%6,%7}, {%8,%9}, {%0,%1,%2,%3};"
                 : "+f"(c[0]), "+f"(c[1]), "+f"(c[2]), "+f"(c[3])
                 : "r"(a[0]), "r"(a[1]), "r"(a[2]), "r"(a[3]), "r"(b0), "r"(b1));
}

// ---- K0: rownorm partials (blocks 0..1023) + scalars/zeroing (block 1024) ----
__global__ void k_init(const float* __restrict__ X,
                       const float* __restrict__ linear,
                       const float* __restrict__ dirv,
                       const float* __restrict__ feat) {
    int t = threadIdx.x;
    if (blockIdx.x == 1024) {
        g_s[t] = 0.f; g_s[FF + t] = 0.f;
        __shared__ float red[256];
        for (int i = 0; i < 2; i++) {
            float pa = feat[i * FF + t] * linear[i * FF + t];
            float pb = dirv[i * FF + t] * linear[i * FF + t];
            red[t] = pa; __syncthreads();
            for (int o = 128; o > 0; o >>= 1) { if (t < o) red[t] += red[t + o]; __syncthreads(); }
            if (t == 0) g_ab[2 * i] = red[0];
            __syncthreads();
            red[t] = pb; __syncthreads();
            for (int o = 128; o > 0; o >>= 1) { if (t < o) red[t] += red[t + o]; __syncthreads(); }
            if (t == 0) g_ab[2 * i + 1] = red[0];
            __syncthreads();
        }
        return;
    }
    int warp = t >> 5, lane = t & 31;
    int row = blockIdx.x * 8 + warp;
    const float* xr = X + row * FF;
    float s = 0.f;
#pragma unroll
    for (int u = 0; u < 8; u++) { float v = xr[lane + 32 * u]; s += v * v; }
#pragma unroll
    for (int o = 16; o > 0; o >>= 1) s += __shfl_xor_sync(0xffffffffu, s, o);
    __shared__ float ws[8];
    if (lane == 0) { ws[warp] = s; g_r[row] = s; }
    __syncthreads();
    if (t == 0) {
        float tt = 0.f;
        for (int w = 0; w < 8; w++) tt += ws[w];
        g_Tp1[blockIdx.x] = tt;
    }
}

// ---- prep: T reduce + alpha inline; Yt[c][j] = bf16(alpha_j*src[j][c]); colsum s ----
__global__ void k_prep(const float* __restrict__ xin, int iter) {
    const float* src = iter ? g_E : xin;
    const float* Tp = iter ? g_Tp2 : g_Tp1;
    int npart = iter ? 128 : 1024;
    __shared__ float red[256];
    __shared__ float sh[64][65];
    __shared__ float csm[64];
    int t = threadIdx.x;
    float tacc = 0.f;
    for (int i = t; i < npart; i += 256) tacc += Tp[i];
    red[t] = tacc; __syncthreads();
    for (int o = 128; o > 0; o >>= 1) { if (t < o) red[t] += red[t + o]; __syncthreads(); }
    float T = red[0];
    __syncthreads();

    float a = g_ab[2 * iter], bb = g_ab[2 * iter + 1];
    float nf = sqrtf(T);
    float sb = (bb >= 0.f) ? 1.f : -1.f;

    int jt = blockIdx.x >> 2;
    int cb = (blockIdx.x & 3) * 64;
    int j0 = jt * 64;
    if (t < 64) csm[t] = 0.f;
    __syncthreads();
    int lr = t >> 4, lc = (t & 15) * 4;
    float ca0 = 0, ca1 = 0, ca2 = 0, ca3 = 0;
#pragma unroll
    for (int w = 0; w < 4; w++) {
        int row = lr + w * 16;
        int J = j0 + row;
        float rJ = iter ? (g_rp[J] + g_rp[NN + J]) : g_r[J];
        float inner = a * sb * rJ / nf;
        float scale = (inner <= 0.f) ? inner : 0.f;
        float al = a - scale * sb / nf;
        if ((blockIdx.x & 3) == 0 && (t & 15) == 0) g_alpha[J] = al;
        float4 v = *(const float4*)&src[J * FF + cb + lc];
        float y0 = al * v.x, y1 = al * v.y, y2 = al * v.z, y3 = al * v.w;
        sh[row][lc] = y0; sh[row][lc + 1] = y1; sh[row][lc + 2] = y2; sh[row][lc + 3] = y3;
        ca0 += y0; ca1 += y1; ca2 += y2; ca3 += y3;
    }
    atomicAdd(&csm[lc], ca0); atomicAdd(&csm[lc + 1], ca1);
    atomicAdd(&csm[lc + 2], ca2); atomicAdd(&csm[lc + 3], ca3);
    __syncthreads();
    int cl = t >> 4, jl = (t & 15) * 4;
#pragma unroll
    for (int w = 0; w < 4; w++) {
        int c = cl + w * 16;
        __nv_bfloat16 p[4];
        p[0] = __float2bfloat16(sh[jl + 0][c]);
        p[1] = __float2bfloat16(sh[jl + 1][c]);
        p[2] = __float2bfloat16(sh[jl + 2][c]);
        p[3] = __float2bfloat16(sh[jl + 3][c]);
        *(uint2*)&g_Yt[(cb + c) * NN + j0 + jl] = *(uint2*)p;
    }
    if (t < 64) atomicAdd(&g_s[iter * FF + cb + t], csm[t]);
}

// ---- SYRK (blocks 0..127) + d-dots (blocks 128..383, overlapped) ----
__global__ __launch_bounds__(256, 2) void k_syrk_d(const float* __restrict__ xin, int iter) {
    int b = blockIdx.x;
    int t = threadIdx.x, lane = t & 31, w = t >> 5;
    if (b >= 128) {
        // d[row] = alpha_row * (src_row . s); 32 rows/block
        const float* src = iter ? g_E : xin;
        __shared__ float s_sh[FF];
        s_sh[t] = g_s[iter * FF + t];
        __syncthreads();
        int idx = b - 128;
#pragma unroll
        for (int rr = 0; rr < 4; rr++) {
            int row = idx * 32 + w * 4 + rr;
            const float* r = &src[row * FF];
            float d = 0.f;
#pragma unroll
            for (int u = 0; u < 8; u++) { int c = lane + 32 * u; d += r[c] * s_sh[c]; }
#pragma unroll
            for (int o = 16; o > 0; o >>= 1) d += __shfl_xor_sync(0xffffffffu, d, o);
            if (lane == 0) g_d[row] = g_alpha[row] * d;
        }
        return;
    }
    __shared__ __nv_bfloat16 Ash[128][72];
    __shared__ __nv_bfloat16 Bsh[128][72];
    int wm = w >> 2, wn = w & 3;
    int chunk = b >> 2;
    int pa = (b >> 1) & 1, pb = b & 1;
    int j0 = chunk * 256;
    float acc[4][4][4];
#pragma unroll
    for (int i = 0; i < 4; i++)
#pragma unroll
        for (int j = 0; j < 4; j++)
#pragma unroll
            for (int q = 0; q < 4; q++) acc[i][j][q] = 0.f;

    for (int ks = 0; ks < 4; ks++) {
        __syncthreads();
#pragma unroll
        for (int u = 0; u < 4; u++) {
            int idx = t + u * 256;
            int row = idx >> 3, g = idx & 7;
            *(uint4*)&Ash[row][g * 8] = *(const uint4*)&g_Yt[(pa * 128 + row) * NN + j0 + ks * 64 + g * 8];
            *(uint4*)&Bsh[row][g * 8] = *(const uint4*)&g_Yt[(pb * 128 + row) * NN + j0 + ks * 64 + g * 8];
        }
        __syncthreads();
#pragma unroll
        for (int kk = 0; kk < 4; kk++) {
            uint32_t a[4][4], bm[2][4];
#pragma unroll
            for (int mi = 0; mi < 4; mi++) {
                int row = wm * 64 + mi * 16 + (lane & 15);
                int col = kk * 16 + 8 * (lane >> 4);
                ldsm4(a[mi], smem_u32(&Ash[row][col]));
            }
#pragma unroll
            for (int p = 0; p < 2; p++) {
                int g = lane >> 3;
                int row = wn * 32 + p * 16 + 8 * (g >> 1) + (lane & 7);
                int col = kk * 16 + 8 * (g & 1);
                ldsm4(bm[p], smem_u32(&Bsh[row][col]));
            }
#pragma unroll
            for (int mi = 0; mi < 4; mi++)
#pragma unroll
                for (int nj = 0; nj < 4; nj++)
                    mma16816(acc[mi][nj], a[mi], bm[nj >> 1][(nj & 1) * 2], bm[nj >> 1][(nj & 1) * 2 + 1]);
        }
    }
    float* gp = &g_Gp[chunk * (FF * FF)];
#pragma unroll
    for (int mi = 0; mi < 4; mi++)
#pragma unroll
        for (int nj = 0; nj < 4; nj++)
#pragma unroll
            for (int gi = 0; gi < 2; gi++) {
                int row = pa * 128 + wm * 64 + mi * 16 + (lane >> 2) + 8 * gi;
                int col = pb * 128 + wn * 32 + nj * 8 + (lane & 3) * 2;
                *(float2*)&gp[row * FF + col] = make_float2(acc[mi][nj][2 * gi], acc[mi][nj][2 * gi + 1]);
            }
}

// ---- Gp reduce -> Gh (blocks 0..255); iter1 adds m = Y^T d (blocks 256..287) ----
__global__ void k_gred_m(int iter) {
    int t = threadIdx.x;
    int b = blockIdx.x;
    if (b < 256) {
        int i = b * 256 + t;
        float sum = 0.f;
#pragma unroll
        for (int ch = 0; ch < 32; ch++) sum += g_Gp[ch * (FF * FF) + i];
        g_Gh[i] = __float2bfloat16(sum);
        return;
    }
    // m_c = sum_j Yt[c][j] * d[j]; warp per feature c
    int w = t >> 5, lane = t & 31;
    int c = (b - 256) * 8 + w;
    const __nv_bfloat16* yc = &g_Yt[c * NN];
    float mm = 0.f;
    for (int jj = 0; jj < 256; jj += 8) {
#pragma unroll
        for (int u = 0; u < 8; u++) {
            int j = lane + (jj + u) * 32;
            mm += __bfloat162float(yc[j]) * g_d[j];
        }
    }
#pragma unroll
    for (int o = 16; o > 0; o >>= 1) mm += __shfl_xor_sync(0xffffffffu, mm, o);
    if (lane == 0) g_m[c] = mm;
}

// ---- update (iter0 only): E = y + (Y.Gh - d*y)/N; r partials, T partials ----
__global__ __launch_bounds__(256, 2) void k_update(const float* __restrict__ src) {
    __shared__ __nv_bfloat16 Ysh[16][136];
    __shared__ __nv_bfloat16 Gsh[128][24];
    __shared__ float rsm[128];
    int t = threadIdx.x, lane = t & 31, w = t >> 5;
    int wm = w >> 2, wn = w & 3;
    int rt = blockIdx.x >> 1, ct = blockIdx.x & 1;
    int rowbase = rt * 128, colbase = ct * 128;
    if (t < 128) rsm[t] = 0.f;
    float acc[4][4][4];
#pragma unroll
    for (int i = 0; i < 4; i++)
#pragma unroll
        for (int j = 0; j < 4; j++)
#pragma unroll
            for (int q = 0; q < 4; q++) acc[i][j][q] = 0.f;

    for (int kk = 0; kk < 16; kk++) {
        __syncthreads();
        {
            int row = t >> 4, g = t & 15;
            *(uint4*)&Ysh[row][g * 8] = *(const uint4*)&g_Yt[(kk * 16 + row) * NN + rowbase + g * 8];
        }
        {
            int n = t >> 1, g = t & 1;
            *(uint4*)&Gsh[n][g * 8] = *(const uint4*)&g_Gh[(colbase + n) * FF + kk * 16 + g * 8];
        }
        __syncthreads();
        uint32_t a[4][4], b[2][4];
#pragma unroll
        for (int mi = 0; mi < 4; mi++) {
            int krow = (lane & 7) + 8 * ((lane >> 4) & 1);
            int mcol = wm * 64 + mi * 16 + 8 * ((lane >> 3) & 1);
            ldsm4t(a[mi], smem_u32(&Ysh[krow][mcol]));
        }
#pragma unroll
        for (int p = 0; p < 2; p++) {
            int g = lane >> 3;
            int row = wn * 32 + p * 16 + 8 * (g >> 1) + (lane & 7);
            int col = 8 * (g & 1);
            ldsm4(b[p], smem_u32(&Gsh[row][col]));
        }
#pragma unroll
        for (int mi = 0; mi < 4; mi++)
#pragma unroll
            for (int nj = 0; nj < 4; nj++)
                mma16816(acc[mi][nj], a[mi], b[nj >> 1][(nj & 1) * 2], b[nj >> 1][(nj & 1) * 2 + 1]);
    }

    const float inv = 1.0f / (float)NN;
    float rowsq[4][2];
#pragma unroll
    for (int i = 0; i < 4; i++) { rowsq[i][0] = 0.f; rowsq[i][1] = 0.f; }

#pragma unroll
    for (int mi = 0; mi < 4; mi++)
#pragma unroll
        for (int gi = 0; gi < 2; gi++) {
            int r = wm * 64 + mi * 16 + (lane >> 2) + 8 * gi;
            int Rg = rowbase + r;
            float al = g_alpha[Rg], dd = g_d[Rg];
#pragma unroll
            for (int nj = 0; nj < 4; nj++) {
                int c = colbase + wn * 32 + nj * 8 + (lane & 3) * 2;
                float2 v = *(const float2*)&src[Rg * FF + c];
                float y0 = al * v.x, y1 = al * v.y;
                float e0 = y0 + (acc[mi][nj][2 * gi] - dd * y0) * inv;
                float e1 = y1 + (acc[mi][nj][2 * gi + 1] - dd * y1) * inv;
                *(float2*)&g_E[Rg * FF + c] = make_float2(e0, e1);
                rowsq[mi][gi] += e0 * e0 + e1 * e1;
            }
        }
#pragma unroll
    for (int mi = 0; mi < 4; mi++)
#pragma unroll
        for (int gi = 0; gi < 2; gi++) {
            float v = rowsq[mi][gi];
            v += __shfl_xor_sync(0xffffffffu, v, 1);
            v += __shfl_xor_sync(0xffffffffu, v, 2);
            if ((lane & 3) == 0) atomicAdd(&rsm[wm * 64 + mi * 16 + (lane >> 2) + 8 * gi], v);
        }
    __syncthreads();
    if (t < 128) g_rp[ct * NN + rowbase + t] = rsm[t];
    if (t == 0) {
        float tt = 0.f;
        for (int i = 0; i < 128; i++) tt += rsm[i];
        g_Tp2[blockIdx.x] = tt;
    }
}

// ---- out: sf = s + (sG - m)/N; u = sf + G sf/N (block-redundant, warp-split);
//      out_j = [alpha_j (src_j.u) - (d_j/N) alpha_j (src_j.sf)] / N ----
__global__ void k_out(float* __restrict__ out) {
    __shared__ float s_sh[FF];
    __shared__ float sf_sh[FF];
    __shared__ float u_sh[FF];
    __shared__ float ps[8][FF];
    int t = threadIdx.x, lane = t & 31, w = t >> 5;
    const float inv = 1.0f / (float)NN;
    s_sh[t] = g_s[FF + t];
    __syncthreads();

    // sg[c] = sum_k s[k] * G[k][c], warp w covers k in [w*32, w*32+32)
    {
        float accp[8];
#pragma unroll
        for (int q = 0; q < 8; q++) accp[q] = 0.f;
        for (int kk = 0; kk < 32; kk++) {
            int k = w * 32 + kk;
            float sk = s_sh[k];
#pragma unroll
            for (int q = 0; q < 8; q++)
                accp[q] += sk * __bfloat162float(g_Gh[k * FF + lane + 32 * q]);
        }
#pragma unroll
        for (int q = 0; q < 8; q++) ps[w][lane + 32 * q] = accp[q];
        __syncthreads();
        float sg = 0.f;
#pragma unroll
        for (int ww = 0; ww < 8; ww++) sg += ps[ww][t];
        sf_sh[t] = s_sh[t] + (sg - g_m[t]) * inv;
        __syncthreads();
    }
    // u[c] = sf[c] + (sum_k sf[k] G[k][c]) / N
    {
        float accp[8];
#pragma unroll
        for (int q = 0; q < 8; q++) accp[q] = 0.f;
        for (int kk = 0; kk < 32; kk++) {
            int k = w * 32 + kk;
            float sk = sf_sh[k];
#pragma unroll
            for (int q = 0; q < 8; q++)
                accp[q] += sk * __bfloat162float(g_Gh[k * FF + lane + 32 * q]);
        }
        __syncthreads();   // protect ps reuse
#pragma unroll
        for (int q = 0; q < 8; q++) ps[w][lane + 32 * q] = accp[q];
        __syncthreads();
        float gu = 0.f;
#pragma unroll
        for (int ww = 0; ww < 8; ww++) gu += ps[ww][t];
        u_sh[t] = sf_sh[t] + gu * inv;
        __syncthreads();
    }

    // 8 warps x 8 rows per block
#pragma unroll
    for (int rr = 0; rr < 8; rr++) {
        int row = blockIdx.x * 64 + w * 8 + rr;
        const float* r = &g_E[row * FF];
        float du = 0.f, dsf = 0.f;
#pragma unroll
        for (int uq = 0; uq < 8; uq++) {
            int c = lane + 32 * uq;
            float v = r[c];
            du += v * u_sh[c];
            dsf += v * sf_sh[c];
        }
#pragma unroll
        for (int o = 16; o > 0; o >>= 1) {
            du += __shfl_xor_sync(0xffffffffu, du, o);
            dsf += __shfl_xor_sync(0xffffffffu, dsf, o);
        }
        if (lane == 0 && row < NN - 1) {
            float al = g_alpha[row], dd = g_d[row];
            out[row] = (al * du - dd * inv * (al * dsf)) * inv;
        }
    }
}

extern "C" void kernel_launch(void* const* d_in, const int* in_sizes, int n_in,
                              void* d_out, int out_size) {
    const float* X      = (const float*)d_in[0];
    const float* linear = (const float*)d_in[2];
    const float* dirv   = (const float*)d_in[3];
    const float* feat   = (const float*)d_in[4];
    float* out = (float*)d_out;

    k_init<<<1025, 256>>>(X, linear, dirv, feat);
    k_prep<<<512, 256>>>(X, 0);
    k_syrk_d<<<384, 256>>>(X, 0);       // SYRK partials + d0 (overlapped)
    k_gred_m<<<256, 256>>>(0);          // Gh
    k_update<<<128, 256>>>(X);          // E, r partials, T partials
    k_prep<<<512, 256>>>(X, 1);
    k_syrk_d<<<384, 256>>>(X, 1);       // SYRK partials + d1
    k_gred_m<<<288, 256>>>(1);          // Gh + m = Y^T d
    k_out<<<128, 256>>>(out);           // sf,u + fused output dots
}

// round 8
// speedup vs baseline: 1.4666x; 1.4666x over previous
#include <cuda_runtime.h>
#include <cuda_bf16.h>
#include <cstdint>

#define NN 8192
#define FF 256

// ---- device scratch ----
__device__ __align__(16) float g_E[NN * FF];             // emb after iter0 (fp32)
__device__ __align__(16) __nv_bfloat16 g_Yt[FF * NN];    // Y^T bf16 [feature][row]
__device__ __align__(16) float g_Gp[32 * FF * FF];       // SYRK split-K partials
__device__ __align__(16) __nv_bfloat16 g_Gh[FF * FF];    // Gram bf16 (symmetric)
__device__ __align__(16) float g_s[2 * FF];              // colsum(Y) per iter
__device__ float g_r[NN];                                // per-row sumsq (iter0)
__device__ float g_rp[2 * NN];                           // per-row sumsq partials (iter1)
__device__ float g_alpha[NN];                            // per-row scale
__device__ float g_d[NN];                                // d_j = alpha_j*(src_j.s)
__device__ float g_Tp1[1024];                            // T partials iter0
__device__ float g_Tp2[128];                             // T partials iter1
__device__ float g_ab[4];                                // a0,b0,a1,b1

// ---- mma / ldmatrix helpers ----
__device__ __forceinline__ uint32_t smem_u32(const void* p) {
    return (uint32_t)__cvta_generic_to_shared(p);
}
__device__ __forceinline__ void ldsm4(uint32_t (&r)[4], uint32_t addr) {
    asm volatile("ldmatrix.sync.aligned.m8n8.x4.shared.b16 {%0,%1,%2,%3}, [%4];"
                 : "=r"(r[0]), "=r"(r[1]), "=r"(r[2]), "=r"(r[3]) : "r"(addr));
}
__device__ __forceinline__ void ldsm4t(uint32_t (&r)[4], uint32_t addr) {
    asm volatile("ldmatrix.sync.aligned.m8n8.x4.trans.shared.b16 {%0,%1,%2,%3}, [%4];"
                 : "=r"(r[0]), "=r"(r[1]), "=r"(r[2]), "=r"(r[3]) : "r"(addr));
}
__device__ __forceinline__ void mma16816(float* c, const uint32_t* a, uint32_t b0, uint32_t b1) {
    asm volatile("mma.sync.aligned.m16n8k16.row.col.f32.bf16.bf16.f32 "
                 "{%0,%1,%2,%3}, {%4,%5,%6,%7}, {%8,%9}, {%0,%1,%2,%3};"
                 : "+f"(c[0]), "+f"(c[1]), "+f"(c[2]), "+f"(c[3])
                 : "r"(a[0]), "r"(a[1]), "r"(a[2]), "r"(a[3]), "r"(b0), "r"(b1));
}

// ---- K0: rownorm partials (blocks 0..1023) + scalars/zeroing (block 1024) ----
__global__ void k_init(const float* __restrict__ X,
                       const float* __restrict__ linear,
                       const float* __restrict__ dirv,
                       const float* __restrict__ feat) {
    int t = threadIdx.x;
    if (blockIdx.x == 1024) {
        g_s[t] = 0.f; g_s[FF + t] = 0.f;
        __shared__ float red[256];
        for (int i = 0; i < 2; i++) {
            float pa = feat[i * FF + t] * linear[i * FF + t];
            float pb = dirv[i * FF + t] * linear[i * FF + t];
            red[t] = pa; __syncthreads();
            for (int o = 128; o > 0; o >>= 1) { if (t < o) red[t] += red[t + o]; __syncthreads(); }
            if (t == 0) g_ab[2 * i] = red[0];
            __syncthreads();
            red[t] = pb; __syncthreads();
            for (int o = 128; o > 0; o >>= 1) { if (t < o) red[t] += red[t + o]; __syncthreads(); }
            if (t == 0) g_ab[2 * i + 1] = red[0];
            __syncthreads();
        }
        return;
    }
    int warp = t >> 5, lane = t & 31;
    int row = blockIdx.x * 8 + warp;
    const float* xr = X + row * FF;
    float s = 0.f;
#pragma unroll
    for (int u = 0; u < 8; u++) { float v = xr[lane + 32 * u]; s += v * v; }
#pragma unroll
    for (int o = 16; o > 0; o >>= 1) s += __shfl_xor_sync(0xffffffffu, s, o);
    __shared__ float ws[8];
    if (lane == 0) { ws[warp] = s; g_r[row] = s; }
    __syncthreads();
    if (t == 0) {
        float tt = 0.f;
        for (int w = 0; w < 8; w++) tt += ws[w];
        g_Tp1[blockIdx.x] = tt;
    }
}

// ---- prep: T reduce + alpha inline; Yt[c][j] = bf16(alpha_j*src[j][c]); colsum s ----
__global__ void k_prep(const float* __restrict__ xin, int iter) {
    const float* src = iter ? g_E : xin;
    const float* Tp = iter ? g_Tp2 : g_Tp1;
    int npart = iter ? 128 : 1024;
    __shared__ float red[256];
    __shared__ float sh[64][65];
    __shared__ float csm[64];
    int t = threadIdx.x;
    float tacc = 0.f;
    for (int i = t; i < npart; i += 256) tacc += Tp[i];
    red[t] = tacc; __syncthreads();
    for (int o = 128; o > 0; o >>= 1) { if (t < o) red[t] += red[t + o]; __syncthreads(); }
    float T = red[0];
    __syncthreads();

    float a = g_ab[2 * iter], bb = g_ab[2 * iter + 1];
    float nf = sqrtf(T);
    float sb = (bb >= 0.f) ? 1.f : -1.f;

    int jt = blockIdx.x >> 2;
    int cb = (blockIdx.x & 3) * 64;
    int j0 = jt * 64;
    if (t < 64) csm[t] = 0.f;
    __syncthreads();
    int lr = t >> 4, lc = (t & 15) * 4;
    float ca0 = 0, ca1 = 0, ca2 = 0, ca3 = 0;
#pragma unroll
    for (int w = 0; w < 4; w++) {
        int row = lr + w * 16;
        int J = j0 + row;
        float rJ = iter ? (g_rp[J] + g_rp[NN + J]) : g_r[J];
        float inner = a * sb * rJ / nf;
        float scale = (inner <= 0.f) ? inner : 0.f;
        float al = a - scale * sb / nf;
        if ((blockIdx.x & 3) == 0 && (t & 15) == 0) g_alpha[J] = al;
        float4 v = *(const float4*)&src[J * FF + cb + lc];
        float y0 = al * v.x, y1 = al * v.y, y2 = al * v.z, y3 = al * v.w;
        sh[row][lc] = y0; sh[row][lc + 1] = y1; sh[row][lc + 2] = y2; sh[row][lc + 3] = y3;
        ca0 += y0; ca1 += y1; ca2 += y2; ca3 += y3;
    }
    atomicAdd(&csm[lc], ca0); atomicAdd(&csm[lc + 1], ca1);
    atomicAdd(&csm[lc + 2], ca2); atomicAdd(&csm[lc + 3], ca3);
    __syncthreads();
    int cl = t >> 4, jl = (t & 15) * 4;
#pragma unroll
    for (int w = 0; w < 4; w++) {
        int c = cl + w * 16;
        __nv_bfloat16 p[4];
        p[0] = __float2bfloat16(sh[jl + 0][c]);
        p[1] = __float2bfloat16(sh[jl + 1][c]);
        p[2] = __float2bfloat16(sh[jl + 2][c]);
        p[3] = __float2bfloat16(sh[jl + 3][c]);
        *(uint2*)&g_Yt[(cb + c) * NN + j0 + jl] = *(uint2*)p;
    }
    if (t < 64) atomicAdd(&g_s[iter * FF + cb + t], csm[t]);
}

// ---- SYRK: Gp[chunk] = partial Y^T Y over 256 rows (bf16 mma); grid (4,32) ----
__global__ __launch_bounds__(256, 2) void k_syrk() {
    __shared__ __nv_bfloat16 Ash[128][72];
    __shared__ __nv_bfloat16 Bsh[128][72];
    int t = threadIdx.x, lane = t & 31, w = t >> 5;
    int wm = w >> 2, wn = w & 3;
    int pa = blockIdx.x >> 1, pb = blockIdx.x & 1;
    int j0 = blockIdx.y * 256;
    float acc[4][4][4];
#pragma unroll
    for (int i = 0; i < 4; i++)
#pragma unroll
        for (int j = 0; j < 4; j++)
#pragma unroll
            for (int q = 0; q < 4; q++) acc[i][j][q] = 0.f;

    for (int ks = 0; ks < 4; ks++) {
        __syncthreads();
#pragma unroll
        for (int u = 0; u < 4; u++) {
            int idx = t + u * 256;
            int row = idx >> 3, g = idx & 7;
            *(uint4*)&Ash[row][g * 8] = *(const uint4*)&g_Yt[(pa * 128 + row) * NN + j0 + ks * 64 + g * 8];
            *(uint4*)&Bsh[row][g * 8] = *(const uint4*)&g_Yt[(pb * 128 + row) * NN + j0 + ks * 64 + g * 8];
        }
        __syncthreads();
#pragma unroll
        for (int kk = 0; kk < 4; kk++) {
            uint32_t a[4][4], b[2][4];
#pragma unroll
            for (int mi = 0; mi < 4; mi++) {
                int row = wm * 64 + mi * 16 + (lane & 15);
                int col = kk * 16 + 8 * (lane >> 4);
                ldsm4(a[mi], smem_u32(&Ash[row][col]));
            }
#pragma unroll
            for (int p = 0; p < 2; p++) {
                int g = lane >> 3;
                int row = wn * 32 + p * 16 + 8 * (g >> 1) + (lane & 7);
                int col = kk * 16 + 8 * (g & 1);
                ldsm4(b[p], smem_u32(&Bsh[row][col]));
            }
#pragma unroll
            for (int mi = 0; mi < 4; mi++)
#pragma unroll
                for (int nj = 0; nj < 4; nj++)
                    mma16816(acc[mi][nj], a[mi], b[nj >> 1][(nj & 1) * 2], b[nj >> 1][(nj & 1) * 2 + 1]);
        }
    }
    float* gp = &g_Gp[blockIdx.y * (FF * FF)];
#pragma unroll
    for (int mi = 0; mi < 4; mi++)
#pragma unroll
        for (int nj = 0; nj < 4; nj++)
#pragma unroll
            for (int gi = 0; gi < 2; gi++) {
                int row = pa * 128 + wm * 64 + mi * 16 + (lane >> 2) + 8 * gi;
                int col = pb * 128 + wn * 32 + nj * 8 + (lane & 3) * 2;
                *(float2*)&gp[row * FF + col] = make_float2(acc[mi][nj][2 * gi], acc[mi][nj][2 * gi + 1]);
            }
}

// ---- fused pass, disjoint blocks run concurrently:
//      blocks 0..255   : Gh = bf16(reduce Gp)
//      blocks 256..1279: d[row] = alpha*(src_row . s), 1 row/warp ----
__global__ void k_gred_dots(const float* __restrict__ xin, int iter) {
    int t = threadIdx.x;
    int b = blockIdx.x;
    if (b < 256) {
        int i = b * 256 + t;
        float sum = 0.f;
#pragma unroll
        for (int ch = 0; ch < 32; ch++) sum += g_Gp[ch * (FF * FF) + i];
        g_Gh[i] = __float2bfloat16(sum);
        return;
    }
    const float* src = iter ? g_E : xin;
    __shared__ float s_sh[FF];
    s_sh[t] = g_s[iter * FF + t];
    __syncthreads();
    int w = t >> 5, lane = t & 31;
    int row = (b - 256) * 8 + w;
    const float* r = &src[row * FF];
    float d = 0.f;
#pragma unroll
    for (int u = 0; u < 8; u++) { int c = lane + 32 * u; d += r[c] * s_sh[c]; }
#pragma unroll
    for (int o = 16; o > 0; o >>= 1) d += __shfl_xor_sync(0xffffffffu, d, o);
    if (lane == 0) g_d[row] = g_alpha[row] * d;
}

// ---- update (iter0 only): E = y + (Y.Gh - d*y)/N; r partials, T partials ----
__global__ __launch_bounds__(256, 2) void k_update(const float* __restrict__ src) {
    __shared__ __nv_bfloat16 Ysh[16][136];
    __shared__ __nv_bfloat16 Gsh[128][24];
    __shared__ float rsm[128];
    int t = threadIdx.x, lane = t & 31, w = t >> 5;
    int wm = w >> 2, wn = w & 3;
    int rt = blockIdx.x >> 1, ct = blockIdx.x & 1;
    int rowbase = rt * 128, colbase = ct * 128;
    if (t < 128) rsm[t] = 0.f;
    float acc[4][4][4];
#pragma unroll
    for (int i = 0; i < 4; i++)
#pragma unroll
        for (int j = 0; j < 4; j++)
#pragma unroll
            for (int q = 0; q < 4; q++) acc[i][j][q] = 0.f;

    for (int kk = 0; kk < 16; kk++) {
        __syncthreads();
        {
            int row = t >> 4, g = t & 15;
            *(uint4*)&Ysh[row][g * 8] = *(const uint4*)&g_Yt[(kk * 16 + row) * NN + rowbase + g * 8];
        }
        {
            int n = t >> 1, g = t & 1;
            *(uint4*)&Gsh[n][g * 8] = *(const uint4*)&g_Gh[(colbase + n) * FF + kk * 16 + g * 8];
        }
        __syncthreads();
        uint32_t a[4][4], b[2][4];
#pragma unroll
        for (int mi = 0; mi < 4; mi++) {
            int krow = (lane & 7) + 8 * ((lane >> 4) & 1);
            int mcol = wm * 64 + mi * 16 + 8 * ((lane >> 3) & 1);
            ldsm4t(a[mi], smem_u32(&Ysh[krow][mcol]));
        }
#pragma unroll
        for (int p = 0; p < 2; p++) {
            int g = lane >> 3;
            int row = wn * 32 + p * 16 + 8 * (g >> 1) + (lane & 7);
            int col = 8 * (g & 1);
            ldsm4(b[p], smem_u32(&Gsh[row][col]));
        }
#pragma unroll
        for (int mi = 0; mi < 4; mi++)
#pragma unroll
            for (int nj = 0; nj < 4; nj++)
                mma16816(acc[mi][nj], a[mi], b[nj >> 1][(nj & 1) * 2], b[nj >> 1][(nj & 1) * 2 + 1]);
    }

    const float inv = 1.0f / (float)NN;
    float rowsq[4][2];
#pragma unroll
    for (int i = 0; i < 4; i++) { rowsq[i][0] = 0.f; rowsq[i][1] = 0.f; }

#pragma unroll
    for (int mi = 0; mi < 4; mi++)
#pragma unroll
        for (int gi = 0; gi < 2; gi++) {
            int r = wm * 64 + mi * 16 + (lane >> 2) + 8 * gi;
            int Rg = rowbase + r;
            float al = g_alpha[Rg], dd = g_d[Rg];
#pragma unroll
            for (int nj = 0; nj < 4; nj++) {
                int c = colbase + wn * 32 + nj * 8 + (lane & 3) * 2;
                float2 v = *(const float2*)&src[Rg * FF + c];
                float y0 = al * v.x, y1 = al * v.y;
                float e0 = y0 + (acc[mi][nj][2 * gi] - dd * y0) * inv;
                float e1 = y1 + (acc[mi][nj][2 * gi + 1] - dd * y1) * inv;
                *(float2*)&g_E[Rg * FF + c] = make_float2(e0, e1);
                rowsq[mi][gi] += e0 * e0 + e1 * e1;
            }
        }
#pragma unroll
    for (int mi = 0; mi < 4; mi++)
#pragma unroll
        for (int gi = 0; gi < 2; gi++) {
            float v = rowsq[mi][gi];
            v += __shfl_xor_sync(0xffffffffu, v, 1);
            v += __shfl_xor_sync(0xffffffffu, v, 2);
            if ((lane & 3) == 0) atomicAdd(&rsm[wm * 64 + mi * 16 + (lane >> 2) + 8 * gi], v);
        }
    __syncthreads();
    if (t < 128) g_rp[ct * NN + rowbase + t] = rsm[t];
    if (t == 0) {
        float tt = 0.f;
        for (int i = 0; i < 128; i++) tt += rsm[i];
        g_Tp2[blockIdx.x] = tt;
    }
}

// ---- out: sf == s1 (colsum invariant under graph block; m = G s exactly).
//      u = s + G s / N (block-redundant, warp-split over k);
//      out_j = [alpha_j (E_j.u) - (d_j/N) alpha_j (E_j.s)] / N ----
__global__ void k_out(float* __restrict__ out) {
    __shared__ float s_sh[FF];
    __shared__ float u_sh[FF];
    __shared__ float ps[8][FF];
    int t = threadIdx.x, lane = t & 31, w = t >> 5;
    const float inv = 1.0f / (float)NN;
    s_sh[t] = g_s[FF + t];
    __syncthreads();

    // gs[c] = sum_k s[k] * G[k][c]; warp w covers k in [w*32, w*32+32)
    float accp[8];
#pragma unroll
    for (int q = 0; q < 8; q++) accp[q] = 0.f;
    for (int kk = 0; kk < 32; kk++) {
        int k = w * 32 + kk;
        float sk = s_sh[k];
#pragma unroll
        for (int q = 0; q < 8; q++)
            accp[q] += sk * __bfloat162float(g_Gh[k * FF + lane + 32 * q]);
    }
#pragma unroll
    for (int q = 0; q < 8; q++) ps[w][lane + 32 * q] = accp[q];
    __syncthreads();
    float gs = 0.f;
#pragma unroll
    for (int ww = 0; ww < 8; ww++) gs += ps[ww][t];
    u_sh[t] = s_sh[t] + gs * inv;
    __syncthreads();

    // 8 warps x 8 rows per block
#pragma unroll
    for (int rr = 0; rr < 8; rr++) {
        int row = blockIdx.x * 64 + w * 8 + rr;
        const float* r = &g_E[row * FF];
        float du = 0.f, ds = 0.f;
#pragma unroll
        for (int uq = 0; uq < 8; uq++) {
            int c = lane + 32 * uq;
            float v = r[c];
            du += v * u_sh[c];
            ds += v * s_sh[c];
        }
#pragma unroll
        for (int o = 16; o > 0; o >>= 1) {
            du += __shfl_xor_sync(0xffffffffu, du, o);
            ds += __shfl_xor_sync(0xffffffffu, ds, o);
        }
        if (lane == 0 && row < NN - 1) {
            float al = g_alpha[row], dd = g_d[row];
            out[row] = (al * du - dd * inv * (al * ds)) * inv;
        }
    }
}

extern "C" void kernel_launch(void* const* d_in, const int* in_sizes, int n_in,
                              void* d_out, int out_size) {
    const float* X      = (const float*)d_in[0];
    const float* linear = (const float*)d_in[2];
    const float* dirv   = (const float*)d_in[3];
    const float* feat   = (const float*)d_in[4];
    float* out = (float*)d_out;

    k_init<<<1025, 256>>>(X, linear, dirv, feat);
    k_prep<<<512, 256>>>(X, 0);
    k_syrk<<<dim3(4, 32), 256>>>();
    k_gred_dots<<<1280, 256>>>(X, 0);     // Gh + d0
    k_update<<<128, 256>>>(X);            // E, r partials, T partials
    k_prep<<<512, 256>>>(X, 1);
    k_syrk<<<dim3(4, 32), 256>>>();
    k_gred_dots<<<1280, 256>>>(X, 1);     // Gh + d1
    k_out<<<128, 256>>>(out);             // u = s + Gs/N + fused output dots
}

// round 9
// speedup vs baseline: 1.5212x; 1.0372x over previous
#include <cuda_runtime.h>
#include <cuda_bf16.h>
#include <cstdint>

#define NN 8192
#define FF 256

// ---- device scratch ----
__device__ __align__(16) float g_E[NN * FF];             // emb after iter0 (fp32)
__device__ __align__(16) __nv_bfloat16 g_Yt[FF * NN];    // Y^T bf16 [feature][row]
__device__ __align__(16) float g_Gp[32 * FF * FF];       // SYRK split-K partials
__device__ __align__(16) __nv_bfloat16 g_Gh[FF * FF];    // Gram bf16 (symmetric)
__device__ __align__(16) float g_s[2 * FF];              // colsum(Y) per iter
__device__ __align__(16) float g_gs[FF];                 // (G s) accum (iter1)
__device__ float g_r[NN];                                // per-row sumsq (iter0)
__device__ float g_rp[2 * NN];                           // per-row sumsq partials (iter1)
__device__ float g_alpha[NN];                            // per-row scale
__device__ float g_Tp1[1024];                            // T partials iter0
__device__ float g_Tp2[128];                             // T partials iter1
__device__ float g_ab[4];                                // a0,b0,a1,b1

// ---- mma / ldmatrix helpers ----
__device__ __forceinline__ uint32_t smem_u32(const void* p) {
    return (uint32_t)__cvta_generic_to_shared(p);
}
__device__ __forceinline__ void ldsm4(uint32_t (&r)[4], uint32_t addr) {
    asm volatile("ldmatrix.sync.aligned.m8n8.x4.shared.b16 {%0,%1,%2,%3}, [%4];"
                 : "=r"(r[0]), "=r"(r[1]), "=r"(r[2]), "=r"(r[3]) : "r"(addr));
}
__device__ __forceinline__ void ldsm4t(uint32_t (&r)[4], uint32_t addr) {
    asm volatile("ldmatrix.sync.aligned.m8n8.x4.trans.shared.b16 {%0,%1,%2,%3}, [%4];"
                 : "=r"(r[0]), "=r"(r[1]), "=r"(r[2]), "=r"(r[3]) : "r"(addr));
}
__device__ __forceinline__ void mma16816(float* c, const uint32_t* a, uint32_t b0, uint32_t b1) {
    asm volatile("mma.sync.aligned.m16n8k16.row.col.f32.bf16.bf16.f32 "
                 "{%0,%1,%2,%3}, {%4,%5,%6,%7}, {%8,%9}, {%0,%1,%2,%3};"
                 : "+f"(c[0]), "+f"(c[1]), "+f"(c[2]), "+f"(c[3])
                 : "r"(a[0]), "r"(a[1]), "r"(a[2]), "r"(a[3]), "r"(b0), "r"(b1));
}

// ---- K0: rownorm partials (blocks 0..1023) + scalars/zeroing (block 1024) ----
__global__ void k_init(const float* __restrict__ X,
                       const float* __restrict__ linear,
                       const float* __restrict__ dirv,
                       const float* __restrict__ feat) {
    int t = threadIdx.x;
    if (blockIdx.x == 1024) {
        g_s[t] = 0.f; g_s[FF + t] = 0.f; g_gs[t] = 0.f;
        __shared__ float red[256];
        for (int i = 0; i < 2; i++) {
            float pa = feat[i * FF + t] * linear[i * FF + t];
            float pb = dirv[i * FF + t] * linear[i * FF + t];
            red[t] = pa; __syncthreads();
            for (int o = 128; o > 0; o >>= 1) { if (t < o) red[t] += red[t + o]; __syncthreads(); }
            if (t == 0) g_ab[2 * i] = red[0];
            __syncthreads();
            red[t] = pb; __syncthreads();
            for (int o = 128; o > 0; o >>= 1) { if (t < o) red[t] += red[t + o]; __syncthreads(); }
            if (t == 0) g_ab[2 * i + 1] = red[0];
            __syncthreads();
        }
        return;
    }
    int warp = t >> 5, lane = t & 31;
    int row = blockIdx.x * 8 + warp;
    const float* xr = X + row * FF;
    float s = 0.f;
#pragma unroll
    for (int u = 0; u < 8; u++) { float v = xr[lane + 32 * u]; s += v * v; }
#pragma unroll
    for (int o = 16; o > 0; o >>= 1) s += __shfl_xor_sync(0xffffffffu, s, o);
    __shared__ float ws[8];
    if (lane == 0) { ws[warp] = s; g_r[row] = s; }
    __syncthreads();
    if (t == 0) {
        float tt = 0.f;
        for (int w = 0; w < 8; w++) tt += ws[w];
        g_Tp1[blockIdx.x] = tt;
    }
}

// ---- prep: T reduce + alpha inline; Yt[c][j] = bf16(alpha_j*src[j][c]); colsum s ----
__global__ void k_prep(const float* __restrict__ xin, int iter) {
    const float* src = iter ? g_E : xin;
    const float* Tp = iter ? g_Tp2 : g_Tp1;
    int npart = iter ? 128 : 1024;
    __shared__ float red[256];
    __shared__ float sh[64][65];
    __shared__ float csm[64];
    int t = threadIdx.x;
    float tacc = 0.f;
    for (int i = t; i < npart; i += 256) tacc += Tp[i];
    red[t] = tacc; __syncthreads();
    for (int o = 128; o > 0; o >>= 1) { if (t < o) red[t] += red[t + o]; __syncthreads(); }
    float T = red[0];
    __syncthreads();

    float a = g_ab[2 * iter], bb = g_ab[2 * iter + 1];
    float nf = sqrtf(T);
    float sb = (bb >= 0.f) ? 1.f : -1.f;

    int jt = blockIdx.x >> 2;
    int cb = (blockIdx.x & 3) * 64;
    int j0 = jt * 64;
    if (t < 64) csm[t] = 0.f;
    __syncthreads();
    int lr = t >> 4, lc = (t & 15) * 4;
    float ca0 = 0, ca1 = 0, ca2 = 0, ca3 = 0;
#pragma unroll
    for (int w = 0; w < 4; w++) {
        int row = lr + w * 16;
        int J = j0 + row;
        float rJ = iter ? (g_rp[J] + g_rp[NN + J]) : g_r[J];
        float inner = a * sb * rJ / nf;
        float scale = (inner <= 0.f) ? inner : 0.f;
        float al = a - scale * sb / nf;
        if ((blockIdx.x & 3) == 0 && (t & 15) == 0) g_alpha[J] = al;
        float4 v = *(const float4*)&src[J * FF + cb + lc];
        float y0 = al * v.x, y1 = al * v.y, y2 = al * v.z, y3 = al * v.w;
        sh[row][lc] = y0; sh[row][lc + 1] = y1; sh[row][lc + 2] = y2; sh[row][lc + 3] = y3;
        ca0 += y0; ca1 += y1; ca2 += y2; ca3 += y3;
    }
    atomicAdd(&csm[lc], ca0); atomicAdd(&csm[lc + 1], ca1);
    atomicAdd(&csm[lc + 2], ca2); atomicAdd(&csm[lc + 3], ca3);
    __syncthreads();
    int cl = t >> 4, jl = (t & 15) * 4;
#pragma unroll
    for (int w = 0; w < 4; w++) {
        int c = cl + w * 16;
        __nv_bfloat16 p[4];
        p[0] = __float2bfloat16(sh[jl + 0][c]);
        p[1] = __float2bfloat16(sh[jl + 1][c]);
        p[2] = __float2bfloat16(sh[jl + 2][c]);
        p[3] = __float2bfloat16(sh[jl + 3][c]);
        *(uint2*)&g_Yt[(cb + c) * NN + j0 + jl] = *(uint2*)p;
    }
    if (t < 64) atomicAdd(&g_s[iter * FF + cb + t], csm[t]);
}

// ---- SYRK: Gp[chunk] = partial Y^T Y over 256 rows (bf16 mma); grid (4,32) ----
__global__ __launch_bounds__(256, 2) void k_syrk() {
    __shared__ __nv_bfloat16 Ash[128][72];
    __shared__ __nv_bfloat16 Bsh[128][72];
    int t = threadIdx.x, lane = t & 31, w = t >> 5;
    int wm = w >> 2, wn = w & 3;
    int pa = blockIdx.x >> 1, pb = blockIdx.x & 1;
    int j0 = blockIdx.y * 256;
    float acc[4][4][4];
#pragma unroll
    for (int i = 0; i < 4; i++)
#pragma unroll
        for (int j = 0; j < 4; j++)
#pragma unroll
            for (int q = 0; q < 4; q++) acc[i][j][q] = 0.f;

    for (int ks = 0; ks < 4; ks++) {
        __syncthreads();
#pragma unroll
        for (int u = 0; u < 4; u++) {
            int idx = t + u * 256;
            int row = idx >> 3, g = idx & 7;
            *(uint4*)&Ash[row][g * 8] = *(const uint4*)&g_Yt[(pa * 128 + row) * NN + j0 + ks * 64 + g * 8];
            *(uint4*)&Bsh[row][g * 8] = *(const uint4*)&g_Yt[(pb * 128 + row) * NN + j0 + ks * 64 + g * 8];
        }
        __syncthreads();
#pragma unroll
        for (int kk = 0; kk < 4; kk++) {
            uint32_t a[4][4], b[2][4];
#pragma unroll
            for (int mi = 0; mi < 4; mi++) {
                int row = wm * 64 + mi * 16 + (lane & 15);
                int col = kk * 16 + 8 * (lane >> 4);
                ldsm4(a[mi], smem_u32(&Ash[row][col]));
            }
#pragma unroll
            for (int p = 0; p < 2; p++) {
                int g = lane >> 3;
                int row = wn * 32 + p * 16 + 8 * (g >> 1) + (lane & 7);
                int col = kk * 16 + 8 * (g & 1);
                ldsm4(b[p], smem_u32(&Bsh[row][col]));
            }
#pragma unroll
            for (int mi = 0; mi < 4; mi++)
#pragma unroll
                for (int nj = 0; nj < 4; nj++)
                    mma16816(acc[mi][nj], a[mi], b[nj >> 1][(nj & 1) * 2], b[nj >> 1][(nj & 1) * 2 + 1]);
        }
    }
    float* gp = &g_Gp[blockIdx.y * (FF * FF)];
#pragma unroll
    for (int mi = 0; mi < 4; mi++)
#pragma unroll
        for (int nj = 0; nj < 4; nj++)
#pragma unroll
            for (int gi = 0; gi < 2; gi++) {
                int row = pa * 128 + wm * 64 + mi * 16 + (lane >> 2) + 8 * gi;
                int col = pb * 128 + wn * 32 + nj * 8 + (lane & 3) * 2;
                *(float2*)&gp[row * FF + col] = make_float2(acc[mi][nj][2 * gi], acc[mi][nj][2 * gi + 1]);
            }
}

// ---- Gp reduce -> Gh; block b owns row b of G. iter1: gs[c] += s[b]*G[b][c] ----
__global__ void k_gred(int iter) {
    int t = threadIdx.x, b = blockIdx.x;
    int i = b * 256 + t;
    float sum = 0.f;
#pragma unroll
    for (int ch = 0; ch < 32; ch++) sum += g_Gp[ch * (FF * FF) + i];
    g_Gh[i] = __float2bfloat16(sum);
    if (iter) {
        float sb = g_s[FF + b];
        atomicAdd(&g_gs[t], sb * sum);
    }
}

// ---- update (iter0): E = y + (Y.Gh - d*y)/N; d = Y.s computed in-loop;
//      r partials, T partials ----
__global__ __launch_bounds__(256, 2) void k_update(const float* __restrict__ src) {
    __shared__ __nv_bfloat16 Ysh[16][136];
    __shared__ __nv_bfloat16 Gsh[128][24];
    __shared__ float s_sh[FF];
    __shared__ float dps[256];
    __shared__ float rsm[128];
    int t = threadIdx.x, lane = t & 31, w = t >> 5;
    int wm = w >> 2, wn = w & 3;
    int rt = blockIdx.x >> 1, ct = blockIdx.x & 1;
    int rowbase = rt * 128, colbase = ct * 128;
    if (t < 128) rsm[t] = 0.f;
    s_sh[t] = g_s[t];
    float dpart = 0.f;
    int dj = t & 127, dhalf = t >> 7;
    float acc[4][4][4];
#pragma unroll
    for (int i = 0; i < 4; i++)
#pragma unroll
        for (int j = 0; j < 4; j++)
#pragma unroll
            for (int q = 0; q < 4; q++) acc[i][j][q] = 0.f;

    for (int kk = 0; kk < 16; kk++) {
        __syncthreads();
        {
            int row = t >> 4, g = t & 15;
            *(uint4*)&Ysh[row][g * 8] = *(const uint4*)&g_Yt[(kk * 16 + row) * NN + rowbase + g * 8];
        }
        {
            int n = t >> 1, g = t & 1;
            *(uint4*)&Gsh[n][g * 8] = *(const uint4*)&g_Gh[(colbase + n) * FF + kk * 16 + g * 8];
        }
        __syncthreads();
        // d accumulation: thread owns (row dj, feature half dhalf)
#pragma unroll
        for (int ff = 0; ff < 8; ff++) {
            int f = dhalf * 8 + ff;
            dpart += __bfloat162float(Ysh[f][dj]) * s_sh[kk * 16 + f];
        }
        uint32_t a[4][4], b[2][4];
#pragma unroll
        for (int mi = 0; mi < 4; mi++) {
            int krow = (lane & 7) + 8 * ((lane >> 4) & 1);
            int mcol = wm * 64 + mi * 16 + 8 * ((lane >> 3) & 1);
            ldsm4t(a[mi], smem_u32(&Ysh[krow][mcol]));
        }
#pragma unroll
        for (int p = 0; p < 2; p++) {
            int g = lane >> 3;
            int row = wn * 32 + p * 16 + 8 * (g >> 1) + (lane & 7);
            int col = 8 * (g & 1);
            ldsm4(b[p], smem_u32(&Gsh[row][col]));
        }
#pragma unroll
        for (int mi = 0; mi < 4; mi++)
#pragma unroll
            for (int nj = 0; nj < 4; nj++)
                mma16816(acc[mi][nj], a[mi], b[nj >> 1][(nj & 1) * 2], b[nj >> 1][(nj & 1) * 2 + 1]);
    }
    dps[t] = dpart;
    __syncthreads();

    const float inv = 1.0f / (float)NN;
    float rowsq[4][2];
#pragma unroll
    for (int i = 0; i < 4; i++) { rowsq[i][0] = 0.f; rowsq[i][1] = 0.f; }

#pragma unroll
    for (int mi = 0; mi < 4; mi++)
#pragma unroll
        for (int gi = 0; gi < 2; gi++) {
            int r = wm * 64 + mi * 16 + (lane >> 2) + 8 * gi;
            int Rg = rowbase + r;
            float al = g_alpha[Rg];
            float dd = dps[r] + dps[r + 128];
#pragma unroll
            for (int nj = 0; nj < 4; nj++) {
                int c = colbase + wn * 32 + nj * 8 + (lane & 3) * 2;
                float2 v = *(const float2*)&src[Rg * FF + c];
                float y0 = al * v.x, y1 = al * v.y;
                float e0 = y0 + (acc[mi][nj][2 * gi] - dd * y0) * inv;
                float e1 = y1 + (acc[mi][nj][2 * gi + 1] - dd * y1) * inv;
                *(float2*)&g_E[Rg * FF + c] = make_float2(e0, e1);
                rowsq[mi][gi] += e0 * e0 + e1 * e1;
            }
        }
#pragma unroll
    for (int mi = 0; mi < 4; mi++)
#pragma unroll
        for (int gi = 0; gi < 2; gi++) {
            float v = rowsq[mi][gi];
            v += __shfl_xor_sync(0xffffffffu, v, 1);
            v += __shfl_xor_sync(0xffffffffu, v, 2);
            if ((lane & 3) == 0) atomicAdd(&rsm[wm * 64 + mi * 16 + (lane >> 2) + 8 * gi], v);
        }
    __syncthreads();
    if (t < 128) g_rp[ct * NN + rowbase + t] = rsm[t];
    if (t == 0) {
        float tt = 0.f;
        for (int i = 0; i < 128; i++) tt += rsm[i];
        g_Tp2[blockIdx.x] = tt;
    }
}

// ---- out: u = s + gs/N; ds = E_j.s; d_j = alpha_j*ds;
//      out_j = [alpha_j (E_j.u) - (d_j/N)(alpha_j ds)] / N ----
__global__ void k_out(float* __restrict__ out) {
    __shared__ float s_sh[FF];
    __shared__ float u_sh[FF];
    int t = threadIdx.x, lane = t & 31, w = t >> 5;
    const float inv = 1.0f / (float)NN;
    float sv = g_s[FF + t];
    s_sh[t] = sv;
    u_sh[t] = sv + g_gs[t] * inv;
    __syncthreads();

    // 8 warps x 8 rows per block
#pragma unroll
    for (int rr = 0; rr < 8; rr++) {
        int row = blockIdx.x * 64 + w * 8 + rr;
        const float* r = &g_E[row * FF];
        float du = 0.f, ds = 0.f;
#pragma unroll
        for (int uq = 0; uq < 8; uq++) {
            int c = lane + 32 * uq;
            float v = r[c];
            du += v * u_sh[c];
            ds += v * s_sh[c];
        }
#pragma unroll
        for (int o = 16; o > 0; o >>= 1) {
            du += __shfl_xor_sync(0xffffffffu, du, o);
            ds += __shfl_xor_sync(0xffffffffu, ds, o);
        }
        if (lane == 0 && row < NN - 1) {
            float al = g_alpha[row];
            float dd = al * ds;
            out[row] = (al * du - dd * inv * (al * ds)) * inv;
        }
    }
}

extern "C" void kernel_launch(void* const* d_in, const int* in_sizes, int n_in,
                              void* d_out, int out_size) {
    const float* X      = (const float*)d_in[0];
    const float* linear = (const float*)d_in[2];
    const float* dirv   = (const float*)d_in[3];
    const float* feat   = (const float*)d_in[4];
    float* out = (float*)d_out;

    k_init<<<1025, 256>>>(X, linear, dirv, feat);
    k_prep<<<512, 256>>>(X, 0);
    k_syrk<<<dim3(4, 32), 256>>>();
    k_gred<<<256, 256>>>(0);
    k_update<<<128, 256>>>(X);            // E, d in-loop, r/T partials
    k_prep<<<512, 256>>>(X, 1);
    k_syrk<<<dim3(4, 32), 256>>>();
    k_gred<<<256, 256>>>(1);              // Gh + gs = G s
    k_out<<<128, 256>>>(out);             // u = s + gs/N, d from ds
}

// round 10
// speedup vs baseline: 1.7033x; 1.1197x over previous
#include <cuda_runtime.h>
#include <cuda_bf16.h>
#include <cstdint>

#define NN 8192
#define FF 256

// ---- device scratch ----
__device__ __align__(16) float g_E[NN * FF];             // emb after iter0 (fp32)
__device__ __align__(16) __nv_bfloat16 g_Yt[FF * NN];    // Y^T bf16 (iter0 only)
__device__ __align__(16) float g_Gp[32 * FF * FF];       // SYRK split-K partials
__device__ __align__(16) __nv_bfloat16 g_Gh[FF * FF];    // Gram bf16 (iter0)
__device__ __align__(16) float g_s[2 * FF];              // colsum(Y) per iter
__device__ __align__(16) float g_gs[FF];                 // gs = G1 s1 accum (iter1)
__device__ float g_r[NN];                                // per-row sumsq (iter0)
__device__ float g_rp[2 * NN];                           // per-row sumsq partials (iter1)
__device__ float g_alpha[NN];                            // per-row scale (alpha0 then alpha1)
__device__ float g_d[NN];                                // w_j (iter1)
__device__ float g_Tp1[1024];                            // T partials iter0
__device__ float g_Tp2[128];                             // T partials iter1
__device__ float g_ab[4];                                // a0,b0,a1,b1

// ---- mma / ldmatrix helpers ----
__device__ __forceinline__ uint32_t smem_u32(const void* p) {
    return (uint32_t)__cvta_generic_to_shared(p);
}
__device__ __forceinline__ void ldsm4(uint32_t (&r)[4], uint32_t addr) {
    asm volatile("ldmatrix.sync.aligned.m8n8.x4.shared.b16 {%0,%1,%2,%3}, [%4];"
                 : "=r"(r[0]), "=r"(r[1]), "=r"(r[2]), "=r"(r[3]) : "r"(addr));
}
__device__ __forceinline__ void ldsm4t(uint32_t (&r)[4], uint32_t addr) {
    asm volatile("ldmatrix.sync.aligned.m8n8.x4.trans.shared.b16 {%0,%1,%2,%3}, [%4];"
                 : "=r"(r[0]), "=r"(r[1]), "=r"(r[2]), "=r"(r[3]) : "r"(addr));
}
__device__ __forceinline__ void mma16816(float* c, const uint32_t* a, uint32_t b0, uint32_t b1) {
    asm volatile("mma.sync.aligned.m16n8k16.row.col.f32.bf16.bf16.f32 "
                 "{%0,%1,%2,%3}, {%4,%5,%6,%7}, {%8,%9}, {%0,%1,%2,%3};"
                 : "+f"(c[0]), "+f"(c[1]), "+f"(c[2]), "+f"(c[3])
                 : "r"(a[0]), "r"(a[1]), "r"(a[2]), "r"(a[3]), "r"(b0), "r"(b1));
}

// ---- K0: rownorm partials (blocks 0..1023) + scalars/zeroing (block 1024) ----
__global__ void k_init(const float* __restrict__ X,
                       const float* __restrict__ linear,
                       const float* __restrict__ dirv,
                       const float* __restrict__ feat) {
    int t = threadIdx.x;
    if (blockIdx.x == 1024) {
        g_s[t] = 0.f; g_s[FF + t] = 0.f; g_gs[t] = 0.f;
        __shared__ float red[256];
        for (int i = 0; i < 2; i++) {
            float pa = feat[i * FF + t] * linear[i * FF + t];
            float pb = dirv[i * FF + t] * linear[i * FF + t];
            red[t] = pa; __syncthreads();
            for (int o = 128; o > 0; o >>= 1) { if (t < o) red[t] += red[t + o]; __syncthreads(); }
            if (t == 0) g_ab[2 * i] = red[0];
            __syncthreads();
            red[t] = pb; __syncthreads();
            for (int o = 128; o > 0; o >>= 1) { if (t < o) red[t] += red[t + o]; __syncthreads(); }
            if (t == 0) g_ab[2 * i + 1] = red[0];
            __syncthreads();
        }
        return;
    }
    int warp = t >> 5, lane = t & 31;
    int row = blockIdx.x * 8 + warp;
    const float* xr = X + row * FF;
    float s = 0.f;
#pragma unroll
    for (int u = 0; u < 8; u++) { float v = xr[lane + 32 * u]; s += v * v; }
#pragma unroll
    for (int o = 16; o > 0; o >>= 1) s += __shfl_xor_sync(0xffffffffu, s, o);
    __shared__ float ws[8];
    if (lane == 0) { ws[warp] = s; g_r[row] = s; }
    __syncthreads();
    if (t == 0) {
        float tt = 0.f;
        for (int w = 0; w < 8; w++) tt += ws[w];
        g_Tp1[blockIdx.x] = tt;
    }
}

// ---- prep (iter0): T reduce + alpha0 inline; Yt = bf16(alpha0*X); colsum s0 ----
__global__ void k_prep(const float* __restrict__ src) {
    __shared__ float red[256];
    __shared__ float sh[64][65];
    __shared__ float csm[64];
    int t = threadIdx.x;
    float tacc = 0.f;
    for (int i = t; i < 1024; i += 256) tacc += g_Tp1[i];
    red[t] = tacc; __syncthreads();
    for (int o = 128; o > 0; o >>= 1) { if (t < o) red[t] += red[t + o]; __syncthreads(); }
    float T = red[0];
    __syncthreads();

    float a = g_ab[0], bb = g_ab[1];
    float nf = sqrtf(T);
    float sb = (bb >= 0.f) ? 1.f : -1.f;

    int jt = blockIdx.x >> 2;
    int cb = (blockIdx.x & 3) * 64;
    int j0 = jt * 64;
    if (t < 64) csm[t] = 0.f;
    __syncthreads();
    int lr = t >> 4, lc = (t & 15) * 4;
    float ca0 = 0, ca1 = 0, ca2 = 0, ca3 = 0;
#pragma unroll
    for (int w = 0; w < 4; w++) {
        int row = lr + w * 16;
        int J = j0 + row;
        float inner = a * sb * g_r[J] / nf;
        float scale = (inner <= 0.f) ? inner : 0.f;
        float al = a - scale * sb / nf;
        if ((blockIdx.x & 3) == 0 && (t & 15) == 0) g_alpha[J] = al;
        float4 v = *(const float4*)&src[J * FF + cb + lc];
        float y0 = al * v.x, y1 = al * v.y, y2 = al * v.z, y3 = al * v.w;
        sh[row][lc] = y0; sh[row][lc + 1] = y1; sh[row][lc + 2] = y2; sh[row][lc + 3] = y3;
        ca0 += y0; ca1 += y1; ca2 += y2; ca3 += y3;
    }
    atomicAdd(&csm[lc], ca0); atomicAdd(&csm[lc + 1], ca1);
    atomicAdd(&csm[lc + 2], ca2); atomicAdd(&csm[lc + 3], ca3);
    __syncthreads();
    int cl = t >> 4, jl = (t & 15) * 4;
#pragma unroll
    for (int w = 0; w < 4; w++) {
        int c = cl + w * 16;
        __nv_bfloat16 p[4];
        p[0] = __float2bfloat16(sh[jl + 0][c]);
        p[1] = __float2bfloat16(sh[jl + 1][c]);
        p[2] = __float2bfloat16(sh[jl + 2][c]);
        p[3] = __float2bfloat16(sh[jl + 3][c]);
        *(uint2*)&g_Yt[(cb + c) * NN + j0 + jl] = *(uint2*)p;
    }
    if (t < 64) atomicAdd(&g_s[cb + t], csm[t]);
}

// ---- SYRK: Gp[chunk] = partial Y^T Y over 256 rows (bf16 mma); grid (4,32) ----
__global__ __launch_bounds__(256, 2) void k_syrk() {
    __shared__ __nv_bfloat16 Ash[128][72];
    __shared__ __nv_bfloat16 Bsh[128][72];
    int t = threadIdx.x, lane = t & 31, w = t >> 5;
    int wm = w >> 2, wn = w & 3;
    int pa = blockIdx.x >> 1, pb = blockIdx.x & 1;
    int j0 = blockIdx.y * 256;
    float acc[4][4][4];
#pragma unroll
    for (int i = 0; i < 4; i++)
#pragma unroll
        for (int j = 0; j < 4; j++)
#pragma unroll
            for (int q = 0; q < 4; q++) acc[i][j][q] = 0.f;

    for (int ks = 0; ks < 4; ks++) {
        __syncthreads();
#pragma unroll
        for (int u = 0; u < 4; u++) {
            int idx = t + u * 256;
            int row = idx >> 3, g = idx & 7;
            *(uint4*)&Ash[row][g * 8] = *(const uint4*)&g_Yt[(pa * 128 + row) * NN + j0 + ks * 64 + g * 8];
            *(uint4*)&Bsh[row][g * 8] = *(const uint4*)&g_Yt[(pb * 128 + row) * NN + j0 + ks * 64 + g * 8];
        }
        __syncthreads();
#pragma unroll
        for (int kk = 0; kk < 4; kk++) {
            uint32_t a[4][4], b[2][4];
#pragma unroll
            for (int mi = 0; mi < 4; mi++) {
                int row = wm * 64 + mi * 16 + (lane & 15);
                int col = kk * 16 + 8 * (lane >> 4);
                ldsm4(a[mi], smem_u32(&Ash[row][col]));
            }
#pragma unroll
            for (int p = 0; p < 2; p++) {
                int g = lane >> 3;
                int row = wn * 32 + p * 16 + 8 * (g >> 1) + (lane & 7);
                int col = kk * 16 + 8 * (g & 1);
                ldsm4(b[p], smem_u32(&Bsh[row][col]));
            }
#pragma unroll
            for (int mi = 0; mi < 4; mi++)
#pragma unroll
                for (int nj = 0; nj < 4; nj++)
                    mma16816(acc[mi][nj], a[mi], b[nj >> 1][(nj & 1) * 2], b[nj >> 1][(nj & 1) * 2 + 1]);
        }
    }
    float* gp = &g_Gp[blockIdx.y * (FF * FF)];
#pragma unroll
    for (int mi = 0; mi < 4; mi++)
#pragma unroll
        for (int nj = 0; nj < 4; nj++)
#pragma unroll
            for (int gi = 0; gi < 2; gi++) {
                int row = pa * 128 + wm * 64 + mi * 16 + (lane >> 2) + 8 * gi;
                int col = pb * 128 + wn * 32 + nj * 8 + (lane & 3) * 2;
                *(float2*)&gp[row * FF + col] = make_float2(acc[mi][nj][2 * gi], acc[mi][nj][2 * gi + 1]);
            }
}

// ---- Gp reduce -> Gh; grid 1024, 4 threads per output x 8 chunks ----
__global__ void k_gred() {
    int t = threadIdx.x, b = blockIdx.x;
    int i = b * 64 + (t >> 2);
    int ch0 = (t & 3) * 8;
    float sum = 0.f;
#pragma unroll
    for (int q = 0; q < 8; q++) sum += g_Gp[(ch0 + q) * (FF * FF) + i];
    sum += __shfl_xor_sync(0xffffffffu, sum, 1);
    sum += __shfl_xor_sync(0xffffffffu, sum, 2);
    if ((t & 3) == 0) g_Gh[i] = __float2bfloat16(sum);
}

// ---- update (iter0): E = y + (Y.Gh - d*y)/N; d = Y.s in-loop; r/T partials ----
__global__ __launch_bounds__(256, 2) void k_update(const float* __restrict__ src) {
    __shared__ __nv_bfloat16 Ysh[16][136];
    __shared__ __nv_bfloat16 Gsh[128][24];
    __shared__ float s_sh[FF];
    __shared__ float dps[256];
    __shared__ float rsm[128];
    int t = threadIdx.x, lane = t & 31, w = t >> 5;
    int wm = w >> 2, wn = w & 3;
    int rt = blockIdx.x >> 1, ct = blockIdx.x & 1;
    int rowbase = rt * 128, colbase = ct * 128;
    if (t < 128) rsm[t] = 0.f;
    s_sh[t] = g_s[t];
    float dpart = 0.f;
    int dj = t & 127, dhalf = t >> 7;
    float acc[4][4][4];
#pragma unroll
    for (int i = 0; i < 4; i++)
#pragma unroll
        for (int j = 0; j < 4; j++)
#pragma unroll
            for (int q = 0; q < 4; q++) acc[i][j][q] = 0.f;

    for (int kk = 0; kk < 16; kk++) {
        __syncthreads();
        {
            int row = t >> 4, g = t & 15;
            *(uint4*)&Ysh[row][g * 8] = *(const uint4*)&g_Yt[(kk * 16 + row) * NN + rowbase + g * 8];
        }
        {
            int n = t >> 1, g = t & 1;
            *(uint4*)&Gsh[n][g * 8] = *(const uint4*)&g_Gh[(colbase + n) * FF + kk * 16 + g * 8];
        }
        __syncthreads();
#pragma unroll
        for (int ff = 0; ff < 8; ff++) {
            int f = dhalf * 8 + ff;
            dpart += __bfloat162float(Ysh[f][dj]) * s_sh[kk * 16 + f];
        }
        uint32_t a[4][4], b[2][4];
#pragma unroll
        for (int mi = 0; mi < 4; mi++) {
            int krow = (lane & 7) + 8 * ((lane >> 4) & 1);
            int mcol = wm * 64 + mi * 16 + 8 * ((lane >> 3) & 1);
            ldsm4t(a[mi], smem_u32(&Ysh[krow][mcol]));
        }
#pragma unroll
        for (int p = 0; p < 2; p++) {
            int g = lane >> 3;
            int row = wn * 32 + p * 16 + 8 * (g >> 1) + (lane & 7);
            int col = 8 * (g & 1);
            ldsm4(b[p], smem_u32(&Gsh[row][col]));
        }
#pragma unroll
        for (int mi = 0; mi < 4; mi++)
#pragma unroll
            for (int nj = 0; nj < 4; nj++)
                mma16816(acc[mi][nj], a[mi], b[nj >> 1][(nj & 1) * 2], b[nj >> 1][(nj & 1) * 2 + 1]);
    }
    dps[t] = dpart;
    __syncthreads();

    const float inv = 1.0f / (float)NN;
    float rowsq[4][2];
#pragma unroll
    for (int i = 0; i < 4; i++) { rowsq[i][0] = 0.f; rowsq[i][1] = 0.f; }

#pragma unroll
    for (int mi = 0; mi < 4; mi++)
#pragma unroll
        for (int gi = 0; gi < 2; gi++) {
            int r = wm * 64 + mi * 16 + (lane >> 2) + 8 * gi;
            int Rg = rowbase + r;
            float al = g_alpha[Rg];
            float dd = dps[r] + dps[r + 128];
#pragma unroll
            for (int nj = 0; nj < 4; nj++) {
                int c = colbase + wn * 32 + nj * 8 + (lane & 3) * 2;
                float2 v = *(const float2*)&src[Rg * FF + c];
                float y0 = al * v.x, y1 = al * v.y;
                float e0 = y0 + (acc[mi][nj][2 * gi] - dd * y0) * inv;
                float e1 = y1 + (acc[mi][nj][2 * gi + 1] - dd * y1) * inv;
                *(float2*)&g_E[Rg * FF + c] = make_float2(e0, e1);
                rowsq[mi][gi] += e0 * e0 + e1 * e1;
            }
        }
#pragma unroll
    for (int mi = 0; mi < 4; mi++)
#pragma unroll
        for (int gi = 0; gi < 2; gi++) {
            float v = rowsq[mi][gi];
            v += __shfl_xor_sync(0xffffffffu, v, 1);
            v += __shfl_xor_sync(0xffffffffu, v, 2);
            if ((lane & 3) == 0) atomicAdd(&rsm[wm * 64 + mi * 16 + (lane >> 2) + 8 * gi], v);
        }
    __syncthreads();
    if (t < 128) g_rp[ct * NN + rowbase + t] = rsm[t];
    if (t == 0) {
        float tt = 0.f;
        for (int i = 0; i < 128; i++) tt += rsm[i];
        g_Tp2[blockIdx.x] = tt;
    }
}

// ---- iter1 pass 1: alpha1 + s1 = colsum(alpha1 . E) ----
__global__ void k_s1() {
    __shared__ float red[256];
    __shared__ float ash[64];
    int t = threadIdx.x;
    float tacc = (t < 128) ? g_Tp2[t] : 0.f;
    red[t] = tacc; __syncthreads();
    for (int o = 128; o > 0; o >>= 1) { if (t < o) red[t] += red[t + o]; __syncthreads(); }
    float T = red[0];
    float a = g_ab[2], bb = g_ab[3];
    float nf = sqrtf(T);
    float sb = (bb >= 0.f) ? 1.f : -1.f;
    int rowbase = blockIdx.x * 64;
    if (t < 64) {
        int J = rowbase + t;
        float rJ = g_rp[J] + g_rp[NN + J];
        float inner = a * sb * rJ / nf;
        float scale = (inner <= 0.f) ? inner : 0.f;
        float al = a - scale * sb / nf;
        g_alpha[J] = al;
        ash[t] = al;
    }
    __syncthreads();
    float cs = 0.f;
#pragma unroll 4
    for (int j = 0; j < 64; j++)
        cs += ash[j] * g_E[(rowbase + j) * FF + t];
    atomicAdd(&g_s[FF + t], cs);
}

// ---- iter1 pass 2: w_j = alpha_j (E_j.s1); gs += sum_j (alpha_j w_j) E_j ----
__global__ void k_wgs() {
    __shared__ float s_sh[FF];
    __shared__ float vsh[64];
    int t = threadIdx.x, lane = t & 31, w = t >> 5;
    int rowbase = blockIdx.x * 64;
    s_sh[t] = g_s[FF + t];
    __syncthreads();
#pragma unroll
    for (int rr = 0; rr < 8; rr++) {
        int r = w * 8 + rr;
        int row = rowbase + r;
        const float* er = &g_E[row * FF];
        float d = 0.f;
#pragma unroll
        for (int u = 0; u < 8; u++) { int c = lane + 32 * u; d += er[c] * s_sh[c]; }
#pragma unroll
        for (int o = 16; o > 0; o >>= 1) d += __shfl_xor_sync(0xffffffffu, d, o);
        if (lane == 0) {
            float al = g_alpha[row];
            float wj = al * d;
            g_d[row] = wj;
            vsh[r] = al * wj;
        }
    }
    __syncthreads();
    float gsp = 0.f;
#pragma unroll 4
    for (int j = 0; j < 64; j++)
        gsp += vsh[j] * g_E[(rowbase + j) * FF + t];
    atomicAdd(&g_gs[t], gsp);
}

// ---- iter1 pass 3: out_j = [w_j + alpha_j (E_j.gs)/N - w_j^2/N] / N ----
__global__ void k_out(float* __restrict__ out) {
    __shared__ float gs_sh[FF];
    int t = threadIdx.x, lane = t & 31, w = t >> 5;
    const float inv = 1.0f / (float)NN;
    gs_sh[t] = g_gs[t];
    __syncthreads();
#pragma unroll
    for (int rr = 0; rr < 8; rr++) {
        int row = blockIdx.x * 64 + w * 8 + rr;
        const float* er = &g_E[row * FF];
        float dgs = 0.f;
#pragma unroll
        for (int u = 0; u < 8; u++) { int c = lane + 32 * u; dgs += er[c] * gs_sh[c]; }
#pragma unroll
        for (int o = 16; o > 0; o >>= 1) dgs += __shfl_xor_sync(0xffffffffu, dgs, o);
        if (lane == 0 && row < NN - 1) {
            float wj = g_d[row];
            float al = g_alpha[row];
            out[row] = (wj + al * dgs * inv - wj * wj * inv) * inv;
        }
    }
}

extern "C" void kernel_launch(void* const* d_in, const int* in_sizes, int n_in,
                              void* d_out, int out_size) {
    const float* X      = (const float*)d_in[0];
    const float* linear = (const float*)d_in[2];
    const float* dirv   = (const float*)d_in[3];
    const float* feat   = (const float*)d_in[4];
    float* out = (float*)d_out;

    k_init<<<1025, 256>>>(X, linear, dirv, feat);
    k_prep<<<512, 256>>>(X);              // alpha0, Yt, s0
    k_syrk<<<dim3(4, 32), 256>>>();       // Gp partials
    k_gred<<<1024, 256>>>();              // Gh (4-way parallel reduce)
    k_update<<<128, 256>>>(X);            // E, d in-loop, r/T partials
    k_s1<<<128, 256>>>();                 // alpha1 + s1
    k_wgs<<<128, 256>>>();                // w + gs = G1 s1 (GEMM-free)
    k_out<<<128, 256>>>(out);             // fused output
}